// round 5
// baseline (speedup 1.0000x reference)
#include <cuda_runtime.h>
#include <math.h>

#define MAIN_BLOCKS 1184
#define MAIN_TPB    256

__device__ float g_part_nll[MAIN_BLOCKS];
__device__ float g_part_w1[MAIN_BLOCKS];
__device__ float g_part_w2[MAIN_BLOCKS];

// picked = label ? p : 1-p, clamped at 1e-8 (reference's eliminate_0), then log.
static __device__ __forceinline__ float pick_log(float p, unsigned int l) {
    float pick = l ? p : (1.0f - p);
    pick = fmaxf(pick, 1e-8f);
    return __logf(pick);
}

static __device__ __forceinline__ float warp_red(float v) {
    #pragma unroll
    for (int o = 16; o; o >>= 1) v += __shfl_down_sync(0xFFFFFFFFu, v, o);
    return v;
}

extern "C" __global__ void __launch_bounds__(MAIN_TPB, 8)
main_kernel(const float4* __restrict__ p4,
            const uint4*  __restrict__ l4,   // labels as int32: 4 per uint4
            const float4* __restrict__ w1,
            const float4* __restrict__ w2,
            int nq, int nw1, int nw2) {
    const int stride = gridDim.x * blockDim.x;
    const int t0 = blockIdx.x * blockDim.x + threadIdx.x;

    float accL = 0.0f;
    // NLL part: one float4 of probs + one uint4 of int32 labels per step.
    for (int i = t0; i < nq; i += stride) {
        float4 p = __ldcs(p4 + i);
        uint4  l = __ldcs(l4 + i);
        accL += pick_log(p.x, l.x);
        accL += pick_log(p.y, l.y);
        accL += pick_log(p.z, l.z);
        accL += pick_log(p.w, l.w);
    }

    float a1 = 0.0f;
    for (int i = t0; i < nw1; i += stride) {
        float4 v = __ldcs(w1 + i);
        a1 = fmaf(v.x, v.x, a1); a1 = fmaf(v.y, v.y, a1);
        a1 = fmaf(v.z, v.z, a1); a1 = fmaf(v.w, v.w, a1);
    }

    float a2 = 0.0f;
    for (int i = t0; i < nw2; i += stride) {
        float4 v = __ldcs(w2 + i);
        a2 = fmaf(v.x, v.x, a2); a2 = fmaf(v.y, v.y, a2);
        a2 = fmaf(v.z, v.z, a2); a2 = fmaf(v.w, v.w, a2);
    }

    // Block reduction of the three accumulators.
    __shared__ float shL[8], sh1[8], sh2[8];
    const int lane = threadIdx.x & 31;
    const int w    = threadIdx.x >> 5;
    accL = warp_red(accL);
    a1   = warp_red(a1);
    a2   = warp_red(a2);
    if (lane == 0) { shL[w] = accL; sh1[w] = a1; sh2[w] = a2; }
    __syncthreads();
    if (w == 0) {
        float vL = (lane < 8) ? shL[lane] : 0.0f;
        float v1 = (lane < 8) ? sh1[lane] : 0.0f;
        float v2 = (lane < 8) ? sh2[lane] : 0.0f;
        vL = warp_red(vL);
        v1 = warp_red(v1);
        v2 = warp_red(v2);
        if (lane == 0) {
            g_part_nll[blockIdx.x] = vL;
            g_part_w1[blockIdx.x]  = v1;
            g_part_w2[blockIdx.x]  = v2;
        }
    }
}

static __device__ __forceinline__ double warp_red_d(double v) {
    #pragma unroll
    for (int o = 16; o; o >>= 1) v += __shfl_down_sync(0xFFFFFFFFu, v, o);
    return v;
}

extern "C" __global__ void __launch_bounds__(1024, 1)
finish_kernel(float* __restrict__ out, double invN) {
    double sL = 0.0, s1 = 0.0, s2 = 0.0;
    for (int i = threadIdx.x; i < MAIN_BLOCKS; i += 1024) {
        sL += (double)g_part_nll[i];
        s1 += (double)g_part_w1[i];
        s2 += (double)g_part_w2[i];
    }
    __shared__ double dL[32], d1[32], d2[32];
    const int lane = threadIdx.x & 31;
    const int w    = threadIdx.x >> 5;
    sL = warp_red_d(sL); s1 = warp_red_d(s1); s2 = warp_red_d(s2);
    if (lane == 0) { dL[w] = sL; d1[w] = s1; d2[w] = s2; }
    __syncthreads();
    if (w == 0) {
        double vL = dL[lane];
        double v1 = d1[lane];
        double v2 = d2[lane];
        vL = warp_red_d(vL); v1 = warp_red_d(v1); v2 = warp_red_d(v2);
        if (lane == 0) {
            double nll = -vL * invN;
            double reg = 0.002 * (sqrt(v1) + sqrt(v2));
            out[0] = (float)(nll + reg);
        }
    }
}

extern "C" void kernel_launch(void* const* d_in, const int* in_sizes, int n_in,
                              void* d_out, int out_size) {
    const float4* p4 = (const float4*)d_in[0];   // output_1: N float32
    const uint4*  l4 = (const uint4*)d_in[1];    // label: N int32 (harness narrows int64)
    const float4* w1 = (const float4*)d_in[2];   // W1: 1024x4096 f32
    const float4* w2 = (const float4*)d_in[3];   // W2: 4096x1024 f32
    const int nq  = in_sizes[0] / 4;   // float4 groups of probs (= uint4 groups of labels)
    const int nw1 = in_sizes[2] / 4;
    const int nw2 = in_sizes[3] / 4;
    const double invN = 1.0 / (double)in_sizes[0];

    main_kernel<<<MAIN_BLOCKS, MAIN_TPB>>>(p4, l4, w1, w2, nq, nw1, nw2);
    finish_kernel<<<1, 1024>>>((float*)d_out, invN);
}